// round 15
// baseline (speedup 1.0000x reference)
#include <cuda_runtime.h>
#include <cuda_bf16.h>
#include <cstdint>

// SSL2d: per-channel sub-pixel bilinear shift with zero padding.
// x: [B=32, C=384, H=56, W=56] fp32, a,b: [C] fp32.
//
// R15: R13 structure (7 rows/thread, MLP=8, shuffle boundary, __stcs stores)
// + L2 evict_last on the x read stream via createpolicy + ld.global.nc.L2::cache_hint
// (sm_103a rejects the immediate .L2::evict_last qualifier on 16B loads; the
// policy-register form is the valid encoding).

#define SSL_H 56
#define SSL_W 56
#define SSL_C 384
#define ROWS_PT 7                           // output rows per thread
#define NRG (SSL_H / ROWS_PT)               // 8 rowgroups
#define NTHREADS (NRG * 16)                 // 128

// L2 evict-last policy (created once per thread, reused for all loads)
__device__ __forceinline__ uint64_t mk_evict_last_policy() {
    uint64_t pol;
    asm volatile("createpolicy.fractional.L2::evict_last.b64 %0, 1.0;" : "=l"(pol));
    return pol;
}

// float4 global load, non-coherent, with L2 cache-hint policy
__device__ __forceinline__ float4 ldg_el(const float* p, uint64_t pol) {
    float4 v;
    asm volatile("ld.global.nc.L2::cache_hint.v4.f32 {%0,%1,%2,%3}, [%4], %5;"
                 : "=f"(v.x), "=f"(v.y), "=f"(v.z), "=f"(v.w)
                 : "l"(p), "l"(pol));
    return v;
}

__global__ __launch_bounds__(NTHREADS, 12)
void ssl2d_kernel(const float* __restrict__ x,
                  const float* __restrict__ a,
                  const float* __restrict__ b,
                  float* __restrict__ out) {
    const int plane = blockIdx.x;           // n * C + c
    const int c = plane - (plane / SSL_C) * SSL_C;

    const float av = __ldg(a + c);
    const float bv = __ldg(b + c);
    const float iaf = floorf(av);
    const float ibf = floorf(bv);
    const float fa = av - iaf;
    const float fb = bv - ibf;
    const int ia = (int)iaf;
    const int ib = (int)ibf;

    const float* __restrict__ xp = x + (size_t)plane * (SSL_H * SSL_W);
    float* __restrict__ op       = out + (size_t)plane * (SSL_H * SSL_W);

    const int tid = threadIdx.x;
    const int j = tid & 15;                 // lane within rowgroup (14,15 idle)
    const int rg = tid >> 4;                // rowgroup 0..7
    const int hbase = rg * ROWS_PT;         // first output row of this thread
    const int w = j << 2;
    const bool active = (j < 14);

    if (ia >= -1 && ia <= 0 && ib >= -1 && ib <= 0) {
        const uint64_t pol = mk_evict_last_policy();

        // ---- fast path: 8 source-row LDG.128 (evict_last) issued up-front ----
        float4 q[ROWS_PT + 1];
        #pragma unroll
        for (int k = 0; k <= ROWS_PT; k++) {
            const int s = hbase + ia + k;
            q[k] = make_float4(0.f, 0.f, 0.f, 0.f);
            if (active & (s >= 0) & (s < SSL_H))
                q[k] = ldg_el(xp + s * SSL_W + w, pol);
        }

        const float fb1 = 1.0f - fb;
        const float fa1 = 1.0f - fa;

        // rolling horizontal blend + vertical blend + store
        float4 Hp;                           // H[k-1]
        #pragma unroll
        for (int k = 0; k <= ROWS_PT; k++) {
            float4 Hc;
            if (ib == 0) {
                float e = __shfl_down_sync(0xffffffffu, q[k].x, 1); // col w+4
                if (j >= 13) e = 0.f;                               // w+4 >= 56
                Hc.x = fb1 * q[k].x + fb * q[k].y;
                Hc.y = fb1 * q[k].y + fb * q[k].z;
                Hc.z = fb1 * q[k].z + fb * q[k].w;
                Hc.w = fb1 * q[k].w + fb * e;
            } else {
                float e = __shfl_up_sync(0xffffffffu, q[k].w, 1);   // col w-1
                if (j == 0) e = 0.f;                                // w-1 < 0
                Hc.x = fb1 * e      + fb * q[k].x;
                Hc.y = fb1 * q[k].x + fb * q[k].y;
                Hc.z = fb1 * q[k].y + fb * q[k].z;
                Hc.w = fb1 * q[k].z + fb * q[k].w;
            }

            if (k > 0 && active) {
                float4 o;
                o.x = fa1 * Hp.x + fa * Hc.x;
                o.y = fa1 * Hp.y + fa * Hc.y;
                o.z = fa1 * Hp.z + fa * Hc.z;
                o.w = fa1 * Hp.w + fa * Hc.w;
                __stcs(reinterpret_cast<float4*>(op + (hbase + k - 1) * SSL_W + w), o);
            }
            Hp = Hc;
        }
    } else if (active) {
        // ---- generic fallback (shifts outside [-1,0]): predicated scalar LDG ----
        const float w00 = (1.0f - fa) * (1.0f - fb);
        const float w01 = (1.0f - fa) * fb;
        const float w10 = fa * (1.0f - fb);
        const float w11 = fa * fb;

        #pragma unroll
        for (int r = 0; r < ROWS_PT; r++) {
            const int h = hbase + r;
            const int h0 = h + ia;
            const int h1 = h0 + 1;
            const bool vh0 = (h0 >= 0) & (h0 < SSL_H);
            const bool vh1 = (h1 >= 0) & (h1 < SSL_H);
            const int wbase = w + ib;
            const float* row0 = xp + h0 * SSL_W;
            const float* row1 = xp + h1 * SSL_W;

            float r0[5], r1[5];
            #pragma unroll
            for (int i = 0; i < 5; i++) {
                const int ws = wbase + i;
                const bool vw = (ws >= 0) & (ws < SSL_W);
                r0[i] = (vh0 & vw) ? __ldg(row0 + ws) : 0.0f;
                r1[i] = (vh1 & vw) ? __ldg(row1 + ws) : 0.0f;
            }

            float4 o;
            o.x = w00 * r0[0] + w01 * r0[1] + w10 * r1[0] + w11 * r1[1];
            o.y = w00 * r0[1] + w01 * r0[2] + w10 * r1[1] + w11 * r1[2];
            o.z = w00 * r0[2] + w01 * r0[3] + w10 * r1[2] + w11 * r1[3];
            o.w = w00 * r0[3] + w01 * r0[4] + w10 * r1[3] + w11 * r1[4];
            __stcs(reinterpret_cast<float4*>(op + h * SSL_W + w), o);
        }
    }
}

extern "C" void kernel_launch(void* const* d_in, const int* in_sizes, int n_in,
                              void* d_out, int out_size) {
    const float* x = (const float*)d_in[0];
    const float* a = (const float*)d_in[1];
    const float* b = (const float*)d_in[2];
    float* out = (float*)d_out;

    const int B = 32;
    const int planes = B * SSL_C;           // 12288
    ssl2d_kernel<<<planes, NTHREADS>>>(x, a, b, out);
}